// round 10
// baseline (speedup 1.0000x reference)
#include <cuda_runtime.h>
#include <cuda_fp16.h>
#include <cstdint>

#define FULL 0xffffffffu

// ---------------- scratch (static __device__, no allocs) ----------------
__device__ __align__(16) __half g2_buf[1024 * 184];
__device__ __align__(16) __half h2_buf[92 * 256 * 2];
__device__ __align__(16) __half feat_h[262144 * 16];
__device__ __align__(16) float  preds_buf[262144];
__device__ __align__(16) float  part_buf[1024 * 32];

// ---------------- f32x2 helpers (base sm_100-family PTX, OK on sm_103) ----------------
__device__ __forceinline__ uint64_t pk2(float lo, float hi) {
    uint64_t d; asm("mov.b64 %0,{%1,%2};" : "=l"(d) : "f"(lo), "f"(hi)); return d;
}
__device__ __forceinline__ float2 upk2(uint64_t v) {
    float2 r; asm("mov.b64 {%0,%1},%2;" : "=f"(r.x), "=f"(r.y) : "l"(v)); return r;
}
__device__ __forceinline__ void fma2(uint64_t& acc, uint64_t a, uint64_t b) {
    asm("fma.rn.f32x2 %0, %1, %2, %0;" : "+l"(acc) : "l"(a), "l"(b));
}

// ---------------- K1: precompute g and h (fp16, pair-packed) ----------------
__global__ void k1_pre(const float* __restrict__ emb, const int* __restrict__ edges,
                       const float* __restrict__ w1, const float* __restrict__ b1)
{
    int idx = blockIdx.x * blockDim.x + threadIdx.x;
    const int NG = 1024 * 188;
    if (idx < NG) {
        int p = idx / 188, r = idx % 188;
        int o = r / 47, j = r % 47;
        if (j >= 46) return;
        int s = p >> 5, t = p & 31;
        const float* es = emb + s * 96 + 2 * j;
        const float* et = emb + t * 96 + 2 * j;
        float v = 0.f;
        #pragma unroll
        for (int k = 0; k < 3; k++) {
            v += w1[o * 12 + 0 * 3 + k] * es[k];
            v += w1[o * 12 + 1 * 3 + k] * et[k];
        }
        g2_buf[p * 184 + (o * 23 + (j >> 1)) * 2 + (j & 1)] = __float2half(v);
    } else {
        int q = idx - NG;
        if (q >= 256 * 188) return;
        int e = q / 188, r = q % 188;
        int o = r / 47, j = r % 47;
        if (j >= 46) return;
        int u = edges[2 * e], vv = edges[2 * e + 1];
        const float* eu = emb + u * 96 + 2 * j;
        const float* ev = emb + vv * 96 + 2 * j;
        float v = b1[o];
        #pragma unroll
        for (int k = 0; k < 3; k++) {
            v += w1[o * 12 + 2 * 3 + k] * eu[k];
            v += w1[o * 12 + 3 * 3 + k] * ev[k];
        }
        h2_buf[((o * 23 + (j >> 1)) * 256 + e) * 2 + (j & 1)] = __float2half(v);
    }
}

// ---------------- K2: conv2/conv3 stack via packed f32x2 FMA ----------------
__global__ void __launch_bounds__(128) k2_feat(
    const float* __restrict__ w2, const float* __restrict__ b2,
    const float* __restrict__ w3, const float* __restrict__ b3)
{
    int sid = blockIdx.x * blockDim.x + threadIdx.x;
    int p = sid >> 8, e = sid & 255;
    const uint32_t* gp = (const uint32_t*)(g2_buf + p * 184);
    const uint32_t* hp = (const uint32_t*)h2_buf;

    // conv2 accumulators: c2[o][m] holds (c0,c1) for pool pair of output m
    uint64_t c2[4][10];
    #pragma unroll
    for (int o = 0; o < 4; o++) {
        float bv = b2[o];
        uint64_t bp = pk2(bv, bv);
        #pragma unroll
        for (int m = 0; m < 10; m++) c2[o][m] = bp;
    }

    #pragma unroll
    for (int i = 0; i < 4; i++) {
        // p1 row i: g+h (HADD2), maxpool2, relu
        float p1r[23];
        #pragma unroll
        for (int j = 0; j < 23; j++) {
            int r = i * 23 + j;
            uint32_t gu = gp[r], hu = hp[r * 256 + e];
            __half2 s = __hadd2(*(__half2*)&gu, *(__half2*)&hu);
            float2 f = __half22float2(s);
            p1r[j] = fmaxf(fmaxf(f.x, f.y), 0.f);
        }
        // adjacent-pair packs (CSE across conv taps)
        uint64_t xp[21];
        #pragma unroll
        for (int j = 0; j < 21; j++) xp[j] = pk2(p1r[j], p1r[j + 1]);
        // broadcast weight packs for this input channel
        uint64_t wp[4][3];
        #pragma unroll
        for (int o = 0; o < 4; o++)
            #pragma unroll
            for (int k = 0; k < 3; k++) {
                float w = w2[o * 12 + i * 3 + k];
                wp[o][k] = pk2(w, w);
            }
        #pragma unroll
        for (int m = 0; m < 10; m++)
            #pragma unroll
            for (int k = 0; k < 3; k++) {
                uint64_t x = xp[2 * m + k];
                #pragma unroll
                for (int o = 0; o < 4; o++) fma2(c2[o][m], wp[o][k], x);
            }
    }
    // pool+relu -> p2
    float p2[4][10];
    #pragma unroll
    for (int o = 0; o < 4; o++)
        #pragma unroll
        for (int m = 0; m < 10; m++) {
            float2 f = upk2(c2[o][m]);
            p2[o][m] = fmaxf(fmaxf(f.x, f.y), 0.f);
        }

    // conv3 accumulators
    uint64_t c3[4][4];
    #pragma unroll
    for (int o = 0; o < 4; o++) {
        float bv = b3[o];
        uint64_t bp = pk2(bv, bv);
        #pragma unroll
        for (int m = 0; m < 4; m++) c3[o][m] = bp;
    }
    #pragma unroll
    for (int i = 0; i < 4; i++) {
        uint64_t xp3[9];
        #pragma unroll
        for (int j = 0; j < 9; j++) xp3[j] = pk2(p2[i][j], p2[i][j + 1]);
        uint64_t wp3[4][3];
        #pragma unroll
        for (int o = 0; o < 4; o++)
            #pragma unroll
            for (int k = 0; k < 3; k++) {
                float w = w3[o * 12 + i * 3 + k];
                wp3[o][k] = pk2(w, w);
            }
        #pragma unroll
        for (int m = 0; m < 4; m++)
            #pragma unroll
            for (int k = 0; k < 3; k++) {
                uint64_t x = xp3[2 * m + k];
                #pragma unroll
                for (int o = 0; o < 4; o++) fma2(c3[o][m], wp3[o][k], x);
            }
    }
    uint32_t pk[8];
    #pragma unroll
    for (int m = 0; m < 4; m++)
        #pragma unroll
        for (int o = 0; o < 4; o++) {
            float2 f = upk2(c3[o][m]);
            float fv = fmaxf(fmaxf(f.x, f.y), 0.f);
            ((__half*)pk)[o * 4 + m] = __float2half(fv);
        }
    uint4* fp = (uint4*)(feat_h + (size_t)sid * 16);
    fp[0] = make_uint4(pk[0], pk[1], pk[2], pk[3]);
    fp[1] = make_uint4(pk[4], pk[5], pk[6], pk[7]);
}

// ================= K3: fused HMMA fp16 MLP, 2 M-tiles per warp =================
static constexpr int OFF_B1 = 0;
static constexpr int OFF_B2 = 4096;
static constexpr int OFF_B3 = OFF_B2 + 65536;
static constexpr int OFF_BIAS = OFF_B3 + 65536;
static constexpr int K3_SMEM = OFF_BIAS + 644 * 4;

__device__ __forceinline__ void mma16816(float& c0, float& c1, float& c2, float& c3,
                                         uint32_t a0, uint32_t a1, uint32_t a2, uint32_t a3,
                                         uint32_t b0, uint32_t b1)
{
    asm volatile(
        "mma.sync.aligned.m16n8k16.row.col.f32.f16.f16.f32 "
        "{%0,%1,%2,%3}, {%4,%5,%6,%7}, {%8,%9}, {%0,%1,%2,%3};"
        : "+f"(c0), "+f"(c1), "+f"(c2), "+f"(c3)
        : "r"(a0), "r"(a1), "r"(a2), "r"(a3), "r"(b0), "r"(b1));
}

// cvt to fp16 pair then relu via HMNMX2 (1 op cheaper than 2x fmaxf)
__device__ __forceinline__ uint32_t packrelu(float x, float y)
{
    __half2 h = __floats2half2_rn(x, y);
    __half2 z = __half2half2(__ushort_as_half((unsigned short)0));
    h = __hmax2(h, z);
    return *(uint32_t*)&h;
}

__device__ __forceinline__ void stage_w(char* smem, int dst, const float* __restrict__ src,
                                        int K, int N, int NT, int tid)
{
    for (int idx = tid; idx < K * N; idx += 256) {
        int k = idx / N, n = idx - k * N;
        int kt = k >> 4, kk = k & 15;
        int t = (kk & 7) >> 1, g = n & 7, nt = n >> 3;
        int lane = g * 4 + t;
        int frag = kt * NT + nt;
        int byte = (frag * 32 + lane) * 8 + ((kk >> 3) & 1) * 4 + (kk & 1) * 2;
        *(__half*)(smem + dst + byte) = __float2half(src[idx]);
    }
}

__global__ void __launch_bounds__(256, 1) k3_mma(
    const float* __restrict__ f1w, const float* __restrict__ f1b,
    const float* __restrict__ f2w, const float* __restrict__ f2b,
    const float* __restrict__ f3w, const float* __restrict__ f3b,
    const float* __restrict__ f4w, const float* __restrict__ f4b)
{
    extern __shared__ char smem[];
    int tid = threadIdx.x;
    int warp = tid >> 5, lane = tid & 31;
    int g = lane >> 2, t = lane & 3;

    stage_w(smem, OFF_B1, f1w,  16, 128, 16, tid);
    stage_w(smem, OFF_B2, f2w, 128, 256, 32, tid);
    stage_w(smem, OFF_B3, f3w, 256, 128, 16, tid);
    float* bias = (float*)(smem + OFF_BIAS);
    if (tid < 128) {
        bias[tid]       = f1b[tid];
        bias[384 + tid] = f3b[tid];
        bias[512 + tid] = f4w[tid];
    }
    if (tid < 256) bias[128 + tid] = f2b[tid];
    if (tid == 0)  bias[640] = f4b[0];
    __syncthreads();

    const uint2* B1f = (const uint2*)(smem + OFF_B1);
    const uint2* B2f = (const uint2*)(smem + OFF_B2);
    const uint2* B3f = (const uint2*)(smem + OFF_B3);
    const float* b1s = bias;
    const float* b2s = bias + 128;
    const float* b3s = bias + 384;
    const float* w4s = bias + 512;
    float b4 = bias[640];

    // tile == pair p; each warp owns 32 rows (two m16 blocks) -> B frag reused x2
    for (int p = blockIdx.x; p < 1024; p += gridDim.x) {
        int base = p * 256 + warp * 32;
        float mask = ((p >> 5) != (p & 31)) ? 1.f : 0.f;

        // ---- A1 fragments for both row blocks ----
        const uint32_t* f0 = (const uint32_t*)(feat_h + (size_t)(base + g) * 16);
        const uint32_t* f1 = (const uint32_t*)(feat_h + (size_t)(base + g + 8) * 16);
        const uint32_t* f2 = (const uint32_t*)(feat_h + (size_t)(base + g + 16) * 16);
        const uint32_t* f3 = (const uint32_t*)(feat_h + (size_t)(base + g + 24) * 16);
        uint32_t aA[4], aB[4];
        aA[0] = f0[t]; aA[1] = f1[t]; aA[2] = f0[t + 4]; aA[3] = f1[t + 4];
        aB[0] = f2[t]; aB[1] = f3[t]; aB[2] = f2[t + 4]; aB[3] = f3[t + 4];

        // ---- fc1: 16 ntiles -> A2 frags (8 ktiles) x 2 blocks ----
        uint32_t A2a[8][4], A2b[8][4];
        uint32_t ea0, ea1, eb0, eb1;
        #pragma unroll
        for (int nt = 0; nt < 16; nt++) {
            const float2 bb = *(const float2*)(b1s + nt * 8 + 2 * t);
            uint2 B = B1f[nt * 32 + lane];
            float c0 = bb.x, c1 = bb.y, c2 = bb.x, c3 = bb.y;
            mma16816(c0, c1, c2, c3, aA[0], aA[1], aA[2], aA[3], B.x, B.y);
            float d0 = bb.x, d1 = bb.y, d2 = bb.x, d3 = bb.y;
            mma16816(d0, d1, d2, d3, aB[0], aB[1], aB[2], aB[3], B.x, B.y);
            uint32_t pa0 = packrelu(c0, c1);
            uint32_t pa1 = packrelu(c2, c3);
            uint32_t pb0 = packrelu(d0, d1);
            uint32_t pb1 = packrelu(d2, d3);
            if (nt & 1) {
                A2a[nt >> 1][0] = ea0; A2a[nt >> 1][1] = ea1;
                A2a[nt >> 1][2] = pa0; A2a[nt >> 1][3] = pa1;
                A2b[nt >> 1][0] = eb0; A2b[nt >> 1][1] = eb1;
                A2b[nt >> 1][2] = pb0; A2b[nt >> 1][3] = pb1;
            } else { ea0 = pa0; ea1 = pa1; eb0 = pb0; eb1 = pb1; }
        }

        // ---- fc2: 32 ntiles, K=128 -> A3 frags (16 ktiles) x 2 blocks ----
        uint32_t A3a[16][4], A3b[16][4];
        #pragma unroll
        for (int nt = 0; nt < 32; nt++) {
            const float2 bb = *(const float2*)(b2s + nt * 8 + 2 * t);
            float c0 = bb.x, c1 = bb.y, c2 = bb.x, c3 = bb.y;
            float d0 = bb.x, d1 = bb.y, d2 = bb.x, d3 = bb.y;
            #pragma unroll
            for (int kt = 0; kt < 8; kt++) {
                uint2 B = B2f[(kt * 32 + nt) * 32 + lane];
                mma16816(c0, c1, c2, c3, A2a[kt][0], A2a[kt][1], A2a[kt][2], A2a[kt][3], B.x, B.y);
                mma16816(d0, d1, d2, d3, A2b[kt][0], A2b[kt][1], A2b[kt][2], A2b[kt][3], B.x, B.y);
            }
            uint32_t pa0 = packrelu(c0, c1);
            uint32_t pa1 = packrelu(c2, c3);
            uint32_t pb0 = packrelu(d0, d1);
            uint32_t pb1 = packrelu(d2, d3);
            if (nt & 1) {
                A3a[nt >> 1][0] = ea0; A3a[nt >> 1][1] = ea1;
                A3a[nt >> 1][2] = pa0; A3a[nt >> 1][3] = pa1;
                A3b[nt >> 1][0] = eb0; A3b[nt >> 1][1] = eb1;
                A3b[nt >> 1][2] = pb0; A3b[nt >> 1][3] = pb1;
            } else { ea0 = pa0; ea1 = pa1; eb0 = pb0; eb1 = pb1; }
        }

        // ---- fc3 + fc4: dual accumulator chains (even/odd kt) x 2 blocks ----
        float rsA0 = 0.f, rsA1 = 0.f, rsB0 = 0.f, rsB1 = 0.f;
        for (int nt = 0; nt < 16; nt++) {
            const float2 bb = *(const float2*)(b3s + nt * 8 + 2 * t);
            float ce0 = bb.x, ce1 = bb.y, ce2 = bb.x, ce3 = bb.y;
            float co0 = 0.f, co1 = 0.f, co2 = 0.f, co3 = 0.f;
            float de0 = bb.x, de1 = bb.y, de2 = bb.x, de3 = bb.y;
            float dq0 = 0.f, dq1 = 0.f, dq2 = 0.f, dq3 = 0.f;
            #pragma unroll
            for (int kt = 0; kt < 8; kt++) {
                uint2 Be = B3f[((2 * kt) * 16 + nt) * 32 + lane];
                uint2 Bo = B3f[((2 * kt + 1) * 16 + nt) * 32 + lane];
                mma16816(ce0, ce1, ce2, ce3, A3a[2 * kt][0], A3a[2 * kt][1], A3a[2 * kt][2], A3a[2 * kt][3], Be.x, Be.y);
                mma16816(co0, co1, co2, co3, A3a[2 * kt + 1][0], A3a[2 * kt + 1][1], A3a[2 * kt + 1][2], A3a[2 * kt + 1][3], Bo.x, Bo.y);
                mma16816(de0, de1, de2, de3, A3b[2 * kt][0], A3b[2 * kt][1], A3b[2 * kt][2], A3b[2 * kt][3], Be.x, Be.y);
                mma16816(dq0, dq1, dq2, dq3, A3b[2 * kt + 1][0], A3b[2 * kt + 1][1], A3b[2 * kt + 1][2], A3b[2 * kt + 1][3], Bo.x, Bo.y);
            }
            float c0 = ce0 + co0, c1 = ce1 + co1, c2 = ce2 + co2, c3 = ce3 + co3;
            float d0 = de0 + dq0, d1 = de1 + dq1, d2 = de2 + dq2, d3 = de3 + dq3;
            const float2 wv = *(const float2*)(w4s + nt * 8 + 2 * t);
            rsA0 += fmaxf(c0, 0.f) * wv.x + fmaxf(c1, 0.f) * wv.y;
            rsA1 += fmaxf(c2, 0.f) * wv.x + fmaxf(c3, 0.f) * wv.y;
            rsB0 += fmaxf(d0, 0.f) * wv.x + fmaxf(d1, 0.f) * wv.y;
            rsB1 += fmaxf(d2, 0.f) * wv.x + fmaxf(d3, 0.f) * wv.y;
        }
        rsA0 += __shfl_xor_sync(FULL, rsA0, 1); rsA0 += __shfl_xor_sync(FULL, rsA0, 2);
        rsA1 += __shfl_xor_sync(FULL, rsA1, 1); rsA1 += __shfl_xor_sync(FULL, rsA1, 2);
        rsB0 += __shfl_xor_sync(FULL, rsB0, 1); rsB0 += __shfl_xor_sync(FULL, rsB0, 2);
        rsB1 += __shfl_xor_sync(FULL, rsB1, 1); rsB1 += __shfl_xor_sync(FULL, rsB1, 2);
        if (t == 0) {
            preds_buf[base + g]      = (rsA0 + b4) * mask;
            preds_buf[base + g + 8]  = (rsA1 + b4) * mask;
            preds_buf[base + g + 16] = (rsB0 + b4) * mask;
            preds_buf[base + g + 24] = (rsB1 + b4) * mask;
        }
    }
}

// ---------------- K4: one block per pair; 8 warps, parallel matvec ----------------
__global__ void __launch_bounds__(256) k4_prop(const int* __restrict__ edges)
{
    __shared__ float W8[8][32][32];
    __shared__ int us[256], vs[256];
    __shared__ float xs[32], red[8][32];
    int tid = threadIdx.x, lane = tid & 31, wid = tid >> 5;
    if (tid < 256) {
        us[tid] = edges[2 * tid];
        vs[tid] = edges[2 * tid + 1];
    }
    int p = blockIdx.x;
    float pr = preds_buf[p * 256 + wid * 32 + lane];
    #pragma unroll
    for (int u = 0; u < 32; u++) W8[wid][u][lane] = 0.f;
    int s = p >> 5;
    if (tid < 32) xs[tid] = (tid == s) ? 1.f : 0.f;
    __syncthreads();

    #pragma unroll
    for (int l = 0; l < 32; l++) {
        int e = wid * 32 + l;
        float prv = __shfl_sync(FULL, pr, l);
        if (vs[e] == lane) W8[wid][us[e]][lane] += prv;
    }
    __syncthreads();

    for (int idx = tid; idx < 1024; idx += 256) {
        float v = ((float*)W8[0])[idx];
        #pragma unroll
        for (int c = 1; c < 8; c++) v += ((float*)W8[c])[idx];
        ((float*)W8[0])[idx] = v;
    }
    __syncthreads();

    float racc = 0.f;
    #pragma unroll
    for (int step = 0; step < 3; step++) {
        float part = 0.f;
        #pragma unroll
        for (int j = 0; j < 4; j++)
            part += W8[0][wid * 4 + j][lane] * xs[wid * 4 + j];
        red[wid][lane] = part;
        __syncthreads();
        if (tid < 32) {
            float xn = red[0][tid];
            #pragma unroll
            for (int c = 1; c < 8; c++) xn += red[c][tid];
            xs[tid] = xn;
        }
        __syncthreads();
        if (tid < 32) racc += xs[tid];
    }
    if (tid < 32) part_buf[p * 32 + tid] = racc;
}

// ---------------- K5: final reduce + normalize ----------------
__global__ void __launch_bounds__(1024) k5_norm(float* __restrict__ out)
{
    __shared__ float red[32][33];
    int tid = threadIdx.x, lane = tid & 31, wid = tid >> 5;
    float ssum = 0.f;
    for (int b = wid; b < 1024; b += 32)
        ssum += part_buf[b * 32 + lane];
    red[wid][lane] = ssum;
    __syncthreads();
    if (tid < 32) {
        float v = 0.f;
        #pragma unroll
        for (int w = 0; w < 32; w++)
            v += red[w][tid];
        float tot = v;
        #pragma unroll
        for (int off = 16; off; off >>= 1)
            tot += __shfl_xor_sync(FULL, tot, off);
        out[tid] = v / tot;
    }
}

// ---------------- launch ----------------
extern "C" void kernel_launch(void* const* d_in, const int* in_sizes, int n_in,
                              void* d_out, int out_size)
{
    const float* emb   = (const float*)d_in[0];
    const int*   edges = (const int*)d_in[1];
    const float* w1 = (const float*)d_in[2];  const float* b1 = (const float*)d_in[3];
    const float* w2 = (const float*)d_in[4];  const float* b2 = (const float*)d_in[5];
    const float* w3 = (const float*)d_in[6];  const float* b3 = (const float*)d_in[7];
    const float* f1w = (const float*)d_in[8];  const float* f1b = (const float*)d_in[9];
    const float* f2w = (const float*)d_in[10]; const float* f2b = (const float*)d_in[11];
    const float* f3w = (const float*)d_in[12]; const float* f3b = (const float*)d_in[13];
    const float* f4w = (const float*)d_in[14]; const float* f4b = (const float*)d_in[15];
    float* out = (float*)d_out;

    cudaFuncSetAttribute(k3_mma, cudaFuncAttributeMaxDynamicSharedMemorySize, K3_SMEM);

    k1_pre<<<1880, 128>>>(emb, edges, w1, b1);
    k2_feat<<<2048, 128>>>(w2, b2, w3, b3);
    k3_mma<<<148, 256, K3_SMEM>>>(f1w, f1b, f2w, f2b, f3w, f3b, f4w, f4b);
    k4_prop<<<1024, 256>>>(edges);
    k5_norm<<<1, 1024>>>(out);
}